// round 17
// baseline (speedup 1.0000x reference)
#include <cuda_runtime.h>

// 5x5 box-filter mean, reflect padding, NCHW fp32, H=W=512.
// R17 = R16 (8 output rows / 12 input rows per thread, 1.5x vertical read
// amplification, two-phase with load/compute overlap) but with an EXPLICIT
// NAMED register window (r0..r7, s0..s3) instead of float4 c[12] accessed
// via pointers -- lets ptxas reuse dead r0..r3 slots for the phase-2 loads.

#define IMG 512
#define TW  128   // tile width  (floats) = 32 lanes * 4
#define TH  32    // tile height (rows)   = 4 warps * 8

__device__ __forceinline__ int refl(int x) {
    return (x < 0) ? -x : ((x >= IMG) ? (2 * IMG - 2 - x) : x);
}

// vertical 5-sum tree over 8 explicit rows -> 4 rows
__device__ __forceinline__ void vsum8e(
    const float4& w0, const float4& w1, const float4& w2, const float4& w3,
    const float4& w4, const float4& w5, const float4& w6, const float4& w7,
    float4* v)
{
    float4 a, b, d;
    a.x = w1.x + w2.x;  a.y = w1.y + w2.y;  a.z = w1.z + w2.z;  a.w = w1.w + w2.w;
    b.x = w3.x + w4.x;  b.y = w3.y + w4.y;  b.z = w3.z + w4.z;  b.w = w3.w + w4.w;
    d.x = w5.x + w6.x;  d.y = w5.y + w6.y;  d.z = w5.z + w6.z;  d.w = w5.w + w6.w;
    v[0].x = w0.x + a.x + b.x;  v[0].y = w0.y + a.y + b.y;
    v[0].z = w0.z + a.z + b.z;  v[0].w = w0.w + a.w + b.w;
    v[1].x = a.x + b.x + w5.x;  v[1].y = a.y + b.y + w5.y;
    v[1].z = a.z + b.z + w5.z;  v[1].w = a.w + b.w + w5.w;
    v[2].x = w2.x + b.x + d.x;  v[2].y = w2.y + b.y + d.y;
    v[2].z = w2.z + b.z + d.z;  v[2].w = w2.w + b.w + d.w;
    v[3].x = b.x + d.x + w7.x;  v[3].y = b.y + d.y + w7.y;
    v[3].z = b.z + d.z + w7.z;  v[3].w = b.w + d.w + w7.w;
}

// halo loads (lanes 0/31) for an 8-row window starting at wbase, then tree
__device__ __forceinline__ void halo8(const float* __restrict__ img,
                                      int wbase, int tile_x, bool interior,
                                      int lane, float2* ve)
{
    #pragma unroll
    for (int k = 0; k < 4; k++) { ve[k].x = 0.f; ve[k].y = 0.f; }
    if (lane == 0 || lane == 31) {
        const bool left = (lane == 0);
        float2 e[8];
        if (left) {
            if (tile_x == 0) {
                #pragma unroll
                for (int k = 0; k < 8; k++) {          // reflect: -2 -> 2, -1 -> 1
                    const float* rp = img + refl(wbase + k) * IMG;
                    e[k].x = rp[2];
                    e[k].y = rp[1];
                }
            } else if (interior) {
                const float* p = img + wbase * IMG + tile_x - 2;
                #pragma unroll
                for (int k = 0; k < 8; k++)
                    e[k] = *reinterpret_cast<const float2*>(p + k * IMG);
            } else {
                #pragma unroll
                for (int k = 0; k < 8; k++)
                    e[k] = *reinterpret_cast<const float2*>(
                        img + refl(wbase + k) * IMG + tile_x - 2);
            }
        } else {
            if (tile_x + TW == IMG) {
                #pragma unroll
                for (int k = 0; k < 8; k++) {          // reflect: 512 -> 510, 513 -> 509
                    const float* rp = img + refl(wbase + k) * IMG;
                    e[k].x = rp[IMG - 2];
                    e[k].y = rp[IMG - 3];
                }
            } else if (interior) {
                const float* p = img + wbase * IMG + tile_x + TW;
                #pragma unroll
                for (int k = 0; k < 8; k++)
                    e[k] = *reinterpret_cast<const float2*>(p + k * IMG);
            } else {
                #pragma unroll
                for (int k = 0; k < 8; k++)
                    e[k] = *reinterpret_cast<const float2*>(
                        img + refl(wbase + k) * IMG + tile_x + TW);
            }
        }
        float2 ae, be, de;
        ae.x = e[1].x + e[2].x;  ae.y = e[1].y + e[2].y;
        be.x = e[3].x + e[4].x;  be.y = e[3].y + e[4].y;
        de.x = e[5].x + e[6].x;  de.y = e[5].y + e[6].y;
        ve[0].x = e[0].x + ae.x + be.x;  ve[0].y = e[0].y + ae.y + be.y;
        ve[1].x = ae.x + be.x + e[5].x;  ve[1].y = ae.y + be.y + e[5].y;
        ve[2].x = e[2].x + be.x + de.x;  ve[2].y = e[2].y + be.y + de.y;
        ve[3].x = be.x + de.x + e[7].x;  ve[3].y = be.y + de.y + e[7].y;
    }
}

__device__ __forceinline__ void shuffle_store4(const float4* v, const float2* ve,
                                               float* obase, int lane)
{
    const float inv25 = 1.0f / 25.0f;
    #pragma unroll
    for (int r = 0; r < 4; r++) {
        float pz = __shfl_up_sync(0xffffffffu, v[r].z, 1);   // col -2
        float pw = __shfl_up_sync(0xffffffffu, v[r].w, 1);   // col -1
        float nx = __shfl_down_sync(0xffffffffu, v[r].x, 1); // col +4
        float ny = __shfl_down_sync(0xffffffffu, v[r].y, 1); // col +5
        if (lane == 0)  { pz = ve[r].x; pw = ve[r].y; }
        if (lane == 31) { nx = ve[r].x; ny = ve[r].y; }

        const float s = v[r].x + v[r].y + v[r].z + v[r].w;
        float4 o;
        o.x = ((s - v[r].w) + pz + pw) * inv25;   // cols -2..2
        o.y = (s + pw) * inv25;                   // cols -1..3
        o.z = (s + nx) * inv25;                   // cols  0..4
        o.w = ((s - v[r].x) + nx + ny) * inv25;   // cols  1..5
        *reinterpret_cast<float4*>(obase + r * IMG) = o;
    }
}

__global__ __launch_bounds__(128)
void box5_kernel(const float* __restrict__ in, float* __restrict__ out)
{
    const int lane = threadIdx.x;       // 0..31 -> float4 column
    const int wrp  = threadIdx.y;       // 0..3  -> 8-row group

    const int tile_x = blockIdx.x * TW;
    const int tile_y = blockIdx.y * TH;
    const float* __restrict__ img  = in  + (size_t)blockIdx.z * (IMG * IMG);
    float* __restrict__       oimg = out + (size_t)blockIdx.z * (IMG * IMG);

    const int colx  = tile_x + lane * 4;
    const int rbase = tile_y + wrp * 8 - 2;   // first of 12 input rows
    const bool interior_y = (rbase >= 0) && (rbase + 11 < IMG);

    float* obase = oimg + (tile_y + wrp * 8) * IMG + colx;

    // ---- Phase 1: load rows 0..7 into named registers ----
    float4 r0, r1, r2, r3, r4, r5, r6, r7;
    if (interior_y) {
        const float* p = img + rbase * IMG + colx;
        r0 = *reinterpret_cast<const float4*>(p + 0 * IMG);
        r1 = *reinterpret_cast<const float4*>(p + 1 * IMG);
        r2 = *reinterpret_cast<const float4*>(p + 2 * IMG);
        r3 = *reinterpret_cast<const float4*>(p + 3 * IMG);
        r4 = *reinterpret_cast<const float4*>(p + 4 * IMG);
        r5 = *reinterpret_cast<const float4*>(p + 5 * IMG);
        r6 = *reinterpret_cast<const float4*>(p + 6 * IMG);
        r7 = *reinterpret_cast<const float4*>(p + 7 * IMG);
    } else {
        r0 = *reinterpret_cast<const float4*>(img + refl(rbase + 0) * IMG + colx);
        r1 = *reinterpret_cast<const float4*>(img + refl(rbase + 1) * IMG + colx);
        r2 = *reinterpret_cast<const float4*>(img + refl(rbase + 2) * IMG + colx);
        r3 = *reinterpret_cast<const float4*>(img + refl(rbase + 3) * IMG + colx);
        r4 = *reinterpret_cast<const float4*>(img + refl(rbase + 4) * IMG + colx);
        r5 = *reinterpret_cast<const float4*>(img + refl(rbase + 5) * IMG + colx);
        r6 = *reinterpret_cast<const float4*>(img + refl(rbase + 6) * IMG + colx);
        r7 = *reinterpret_cast<const float4*>(img + refl(rbase + 7) * IMG + colx);
    }

    // vsum rows 0..3 (r0..r3 die after this)
    float4 v[4];
    vsum8e(r0, r1, r2, r3, r4, r5, r6, r7, v);

    // ---- Phase 2 loads (rows 8..11) -> s0..s3, reusing dead slots ----
    float4 s0, s1, s2, s3;
    if (interior_y) {
        const float* p = img + (rbase + 8) * IMG + colx;
        s0 = *reinterpret_cast<const float4*>(p + 0 * IMG);
        s1 = *reinterpret_cast<const float4*>(p + 1 * IMG);
        s2 = *reinterpret_cast<const float4*>(p + 2 * IMG);
        s3 = *reinterpret_cast<const float4*>(p + 3 * IMG);
    } else {
        s0 = *reinterpret_cast<const float4*>(img + refl(rbase + 8)  * IMG + colx);
        s1 = *reinterpret_cast<const float4*>(img + refl(rbase + 9)  * IMG + colx);
        s2 = *reinterpret_cast<const float4*>(img + refl(rbase + 10) * IMG + colx);
        s3 = *reinterpret_cast<const float4*>(img + refl(rbase + 11) * IMG + colx);
    }

    // ---- Phase 1 tail: halo (L1 hits), shuffles, stores rows 0..3 ----
    float2 ve[4];
    halo8(img, rbase, tile_x, interior_y, lane, ve);
    shuffle_store4(v, ve, obase, lane);

    // ---- Phase 2: vsum rows 4..7 on window (r4..r7, s0..s3), halo, store ----
    vsum8e(r4, r5, r6, r7, s0, s1, s2, s3, v);
    halo8(img, rbase + 4, tile_x, interior_y, lane, ve);
    shuffle_store4(v, ve, obase + 4 * IMG, lane);
}

extern "C" void kernel_launch(void* const* d_in, const int* in_sizes, int n_in,
                              void* d_out, int out_size)
{
    const float* in = (const float*)d_in[0];
    float* out = (float*)d_out;

    const int planes = in_sizes[0] / (IMG * IMG);   // 96

    dim3 grid(IMG / TW, IMG / TH, planes);          // (4, 16, 96) = 6144
    dim3 block(32, 4);
    box5_kernel<<<grid, block>>>(in, out);
}